// round 5
// baseline (speedup 1.0000x reference)
#include <cuda_runtime.h>

#define BB 8
#define HH 128
#define WW 128

// Workspaces: (B, S, P, C) with C contiguous. 64 MB each.
__device__ float g_ws1[(size_t)BB * HH * WW * 128];
__device__ float g_ws2[(size_t)BB * HH * WW * 128];

typedef unsigned long long ull;

#define MT 32      // positions per block
#define NT 32      // out-channels per block
#define AROW 129   // A row stride (odd => conflict-free strided row access)
#define NROWS 40   // MT + 8 halo rows

// ---------------------------------------------------------------------------
// One directional-scan step:
//   y[b,s_cur,p,oc] += relu( sum_{kw,ic} y[b,s_prev,p+kw-4,ic] * W9[kw,ic,oc] )
// Grid: 128 blocks (4 wtile x 4 octile x 8 batch) -> ONE wave on 148 SMs.
// Block: 256 threads = 8 warps, 8-way K-split (warp w -> ic [16w,16w+16)).
// Every warp computes the full 32pos x 32oc tile over its ic slice.
// Lane micro-tile: 4 pos x 8 oc, f32x2 packed accumulators (16 FFMA2/ic).
// Log2 cross-warp reduction through smem, epilogue by warp 0.
// ---------------------------------------------------------------------------
template <int WS>
__global__ __launch_bounds__(256) void step_kernel(const float* __restrict__ W9,
                                                   int s_cur, int s_prev)
{
    float* y = WS ? g_ws2 : g_ws1;

    __shared__ __align__(16) float Bs[128 * NT];       // 16KB  W9[kw] slice
    __shared__ __align__(16) float As[NROWS * AROW];   // 20.6KB window (Rs aliases)

    const int tid  = threadIdx.x;
    const int wid  = tid >> 5;       // 0..7  -> ic slice
    const int lane = tid & 31;
    const int pg   = lane >> 2;      // 0..7 -> positions 4pg..4pg+3
    const int og   = lane & 3;       // 0..3 -> oc 8og..8og+7
    const int ic0  = wid * 16;
    const int p0   = blockIdx.x * MT;
    const int oc0  = blockIdx.y * NT;
    const int b    = blockIdx.z;

    const float* prev = y + (((size_t)b * 128 + s_prev) * 128) * 128;

    // ---- Stage A window (rows p0-4 .. p0+35, zero-padded) ----
    #pragma unroll
    for (int q = 0; q < 5; ++q) {
        int idx = tid + 256 * q;        // 1280 float4s
        int r = idx >> 5, j = idx & 31;
        int gp = p0 - 4 + r;
        float4 v = make_float4(0.f, 0.f, 0.f, 0.f);
        if (gp >= 0 && gp < 128) v = *(const float4*)(prev + (size_t)gp * 128 + j * 4);
        float* d = &As[r * AROW + j * 4];
        d[0] = v.x; d[1] = v.y; d[2] = v.z; d[3] = v.w;
    }

    // ---- Stage B[kw=0]: 128ic x 32oc = 16KB, 4 float4 per thread ----
    const float* wbase = W9 + oc0;
    float4 wreg[4];
    #pragma unroll
    for (int q = 0; q < 4; ++q) {
        int j = tid + 256 * q;
        wreg[q] = *(const float4*)(wbase + (size_t)(j >> 3) * 128 + (j & 7) * 4);
    }
    #pragma unroll
    for (int q = 0; q < 4; ++q)
        *(float4*)&Bs[(tid + 256 * q) * 4] = wreg[q];
    __syncthreads();

    ull acc[4][4];
    #pragma unroll
    for (int p = 0; p < 4; ++p)
        #pragma unroll
        for (int q = 0; q < 4; ++q) acc[p][q] = 0ull;

    for (int kw = 0; kw < 9; ++kw) {
        // Prefetch next kw's weights into registers (LDG overlaps compute).
        if (kw < 8) {
            const float* wk = wbase + (size_t)(kw + 1) * 16384;
            #pragma unroll
            for (int q = 0; q < 4; ++q) {
                int j = tid + 256 * q;
                wreg[q] = *(const float4*)(wk + (size_t)(j >> 3) * 128 + (j & 7) * 4);
            }
        }

        const float* Ar = &As[(4 * pg + kw) * AROW + ic0];
        const float* Bp = &Bs[ic0 * NT + 8 * og];

        #pragma unroll
        for (int i = 0; i < 16; ++i) {
            float a0 = Ar[i];
            float a1 = Ar[i + AROW];
            float a2 = Ar[i + 2 * AROW];
            float a3 = Ar[i + 3 * AROW];
            ull d0, d1, d2, d3;
            asm("mov.b64 %0, {%1, %1};" : "=l"(d0) : "f"(a0));
            asm("mov.b64 %0, {%1, %1};" : "=l"(d1) : "f"(a1));
            asm("mov.b64 %0, {%1, %1};" : "=l"(d2) : "f"(a2));
            asm("mov.b64 %0, {%1, %1};" : "=l"(d3) : "f"(a3));
            ulonglong2 bx = *(const ulonglong2*)(Bp + i * NT);      // oc 0..3
            ulonglong2 by = *(const ulonglong2*)(Bp + i * NT + 4);  // oc 4..7
            asm("fma.rn.f32x2 %0, %1, %2, %0;" : "+l"(acc[0][0]) : "l"(d0), "l"(bx.x));
            asm("fma.rn.f32x2 %0, %1, %2, %0;" : "+l"(acc[0][1]) : "l"(d0), "l"(bx.y));
            asm("fma.rn.f32x2 %0, %1, %2, %0;" : "+l"(acc[0][2]) : "l"(d0), "l"(by.x));
            asm("fma.rn.f32x2 %0, %1, %2, %0;" : "+l"(acc[0][3]) : "l"(d0), "l"(by.y));
            asm("fma.rn.f32x2 %0, %1, %2, %0;" : "+l"(acc[1][0]) : "l"(d1), "l"(bx.x));
            asm("fma.rn.f32x2 %0, %1, %2, %0;" : "+l"(acc[1][1]) : "l"(d1), "l"(bx.y));
            asm("fma.rn.f32x2 %0, %1, %2, %0;" : "+l"(acc[1][2]) : "l"(d1), "l"(by.x));
            asm("fma.rn.f32x2 %0, %1, %2, %0;" : "+l"(acc[1][3]) : "l"(d1), "l"(by.y));
            asm("fma.rn.f32x2 %0, %1, %2, %0;" : "+l"(acc[2][0]) : "l"(d2), "l"(bx.x));
            asm("fma.rn.f32x2 %0, %1, %2, %0;" : "+l"(acc[2][1]) : "l"(d2), "l"(bx.y));
            asm("fma.rn.f32x2 %0, %1, %2, %0;" : "+l"(acc[2][2]) : "l"(d2), "l"(by.x));
            asm("fma.rn.f32x2 %0, %1, %2, %0;" : "+l"(acc[2][3]) : "l"(d2), "l"(by.y));
            asm("fma.rn.f32x2 %0, %1, %2, %0;" : "+l"(acc[3][0]) : "l"(d3), "l"(bx.x));
            asm("fma.rn.f32x2 %0, %1, %2, %0;" : "+l"(acc[3][1]) : "l"(d3), "l"(bx.y));
            asm("fma.rn.f32x2 %0, %1, %2, %0;" : "+l"(acc[3][2]) : "l"(d3), "l"(by.x));
            asm("fma.rn.f32x2 %0, %1, %2, %0;" : "+l"(acc[3][3]) : "l"(d3), "l"(by.y));
        }

        __syncthreads();                 // all warps done reading Bs
        if (kw < 8) {
            #pragma unroll
            for (int q = 0; q < 4; ++q)
                *(float4*)&Bs[(tid + 256 * q) * 4] = wreg[q];
        }
        __syncthreads();
    }

    // ---- Log2 cross-warp reduction. Rs aliases As (needs <= 16KB live). ----
    // Layout: Rs[slot][pq][lane] — element-major so each warp-wide ull
    // store/load hits 32 consecutive banks (conflict-free).
    float* Rs = As;

    auto dump = [&](int slot) {
        float* base = Rs + slot * 1024 + lane * 2;
        #pragma unroll
        for (int p = 0; p < 4; ++p)
            #pragma unroll
            for (int q = 0; q < 4; ++q)
                *(ull*)(base + (p * 4 + q) * 64) = acc[p][q];
    };
    auto gather = [&](int slot) {
        const float* base = Rs + slot * 1024 + lane * 2;
        #pragma unroll
        for (int p = 0; p < 4; ++p)
            #pragma unroll
            for (int q = 0; q < 4; ++q) {
                ull v = *(const ull*)(base + (p * 4 + q) * 64);
                asm("add.rn.f32x2 %0, %0, %1;" : "+l"(acc[p][q]) : "l"(v));
            }
    };

    if (wid >= 4) dump(wid - 4);
    __syncthreads();
    if (wid < 4) gather(wid);
    __syncthreads();
    if (wid == 2 || wid == 3) dump(wid - 2);
    __syncthreads();
    if (wid < 2) gather(wid);
    __syncthreads();
    if (wid == 1) dump(0);
    __syncthreads();

    if (wid == 0) {
        gather(0);
        // Epilogue: lane owns 4 pos x 8 oc. RMW + relu.
        #pragma unroll
        for (int p = 0; p < 4; ++p) {
            int pos = p0 + 4 * pg + p;
            float* dst = y + (((size_t)b * 128 + s_cur) * 128 + pos) * 128 + oc0 + 8 * og;
            float r0, r1, r2, r3, r4, r5, r6, r7;
            asm("mov.b64 {%0, %1}, %2;" : "=f"(r0), "=f"(r1) : "l"(acc[p][0]));
            asm("mov.b64 {%0, %1}, %2;" : "=f"(r2), "=f"(r3) : "l"(acc[p][1]));
            asm("mov.b64 {%0, %1}, %2;" : "=f"(r4), "=f"(r5) : "l"(acc[p][2]));
            asm("mov.b64 {%0, %1}, %2;" : "=f"(r6), "=f"(r7) : "l"(acc[p][3]));
            float4 c0 = *(float4*)dst;
            float4 c1 = *(float4*)(dst + 4);
            c0.x += fmaxf(r0, 0.f); c0.y += fmaxf(r1, 0.f);
            c0.z += fmaxf(r2, 0.f); c0.w += fmaxf(r3, 0.f);
            c1.x += fmaxf(r4, 0.f); c1.y += fmaxf(r5, 0.f);
            c1.z += fmaxf(r6, 0.f); c1.w += fmaxf(r7, 0.f);
            *(float4*)dst = c0;
            *(float4*)(dst + 4) = c1;
        }
    }
}

// ---------------------------------------------------------------------------
// Transposes (not on the critical path)
// ---------------------------------------------------------------------------
__global__ void t_in(const float* __restrict__ x)
{
    __shared__ float t[32][33];
    const int bh = blockIdx.z;
    const int b = bh >> 7, h = bh & 127;
    const int w0 = blockIdx.x * 32;
    const int c0 = blockIdx.y * 32;
    const int tx = threadIdx.x, ty = threadIdx.y;

    const float* src = x + (((size_t)b * 128 + c0) * 128 + h) * 128 + w0;
    #pragma unroll
    for (int i = 0; i < 4; ++i) {
        int c = ty * 4 + i;
        t[c][tx] = src[(size_t)c * 128 * 128 + tx];
    }
    __syncthreads();
    float* d = g_ws1 + (((size_t)b * 128 + h) * 128 + w0) * 128 + c0;
    #pragma unroll
    for (int i = 0; i < 4; ++i) {
        int w = ty * 4 + i;
        d[(size_t)w * 128 + tx] = t[tx][w];
    }
}

__global__ void t_mid()
{
    const int b = blockIdx.z;
    const int h = blockIdx.y;
    const int w = blockIdx.x * blockDim.y + threadIdx.y;
    const int c4 = threadIdx.x;
    const float4* s = (const float4*)(g_ws1 + (((size_t)b * 128 + h) * 128 + w) * 128);
    float4* d = (float4*)(g_ws2 + (((size_t)b * 128 + w) * 128 + h) * 128);
    d[c4] = s[c4];
}

__global__ void t_out(float* __restrict__ out)
{
    __shared__ float t[32][33];
    const int bh = blockIdx.z;
    const int b = bh >> 7, h = bh & 127;
    const int w0 = blockIdx.x * 32;
    const int c0 = blockIdx.y * 32;
    const int tx = threadIdx.x, ty = threadIdx.y;

    const float* src = g_ws2 + (((size_t)b * 128 + w0) * 128 + h) * 128 + c0;
    #pragma unroll
    for (int i = 0; i < 4; ++i) {
        int w = ty * 4 + i;
        t[w][tx] = src[(size_t)w * 128 * 128 + tx];
    }
    __syncthreads();
    float* d = out + (((size_t)b * 128 + c0) * 128 + h) * 128 + w0;
    #pragma unroll
    for (int i = 0; i < 4; ++i) {
        int c = ty * 4 + i;
        d[(size_t)c * 128 * 128 + tx] = t[tx][c];
    }
}

// ---------------------------------------------------------------------------
// Launch
// ---------------------------------------------------------------------------
extern "C" void kernel_launch(void* const* d_in, const int* in_sizes, int n_in,
                              void* d_out, int out_size)
{
    const float* x    = (const float*)d_in[0];
    const float* k_td = (const float*)d_in[1];
    const float* k_dt = (const float*)d_in[2];
    const float* k_lr = (const float*)d_in[3];
    const float* k_rl = (const float*)d_in[4];
    float* out = (float*)d_out;

    const dim3 tb(32, 8);
    const dim3 tg(4, 4, BB * HH);
    const dim3 sg(WW / MT, 128 / NT, BB);   // (4, 4, 8) = 128 blocks: ONE wave

    t_in<<<tg, tb>>>(x);

    for (int s = 1; s < HH; ++s)
        step_kernel<0><<<sg, 256>>>(k_td, s, s - 1);
    for (int s = HH - 2; s >= 0; --s)
        step_kernel<0><<<sg, 256>>>(k_dt, s, s + 1);

    t_mid<<<dim3(32, 128, BB), dim3(32, 4)>>>();

    for (int s = 1; s < WW; ++s)
        step_kernel<1><<<sg, 256>>>(k_lr, s, s - 1);
    for (int s = WW - 2; s >= 0; --s)
        step_kernel<1><<<sg, 256>>>(k_rl, s, s + 1);

    t_out<<<tg, tb>>>(out);
}

// round 7
// speedup vs baseline: 1.3261x; 1.3261x over previous
#include <cuda_runtime.h>
#include <cuda_bf16.h>

#define BB 8
#define HH 128
typedef unsigned int u32;

// fp32 workspaces (ground truth) + bf16 hi/lo planes (MMA operands)
__device__ float g_ws1[(size_t)BB*128*128*128];
__device__ float g_ws2[(size_t)BB*128*128*128];
__device__ __align__(256) __nv_bfloat16 g_p1h[(size_t)BB*128*128*128];
__device__ __align__(256) __nv_bfloat16 g_p1l[(size_t)BB*128*128*128];
__device__ __align__(256) __nv_bfloat16 g_p2h[(size_t)BB*128*128*128];
__device__ __align__(256) __nv_bfloat16 g_p2l[(size_t)BB*128*128*128];
// Split weights, ORIGINAL layout [dir*9+kw][ic][oc]
__device__ __align__(256) __nv_bfloat16 g_wh[(size_t)36*128*128];
__device__ __align__(256) __nv_bfloat16 g_wl[(size_t)36*128*128];

// ---------------- helpers ----------------
__device__ __forceinline__ u32 smem_u32(const void* p){
    u32 a; asm("{ .reg .u64 t; cvta.to.shared.u64 t, %1; cvt.u32.u64 %0, t; }":"=r"(a):"l"(p)); return a;
}
__device__ __forceinline__ void cpa16(u32 d, const void* g){
    asm volatile("cp.async.ca.shared.global [%0],[%1],16;\n"::"r"(d),"l"(g));
}
__device__ __forceinline__ void sts16z(u32 d){
    asm volatile("st.shared.v4.b32 [%0],{%1,%1,%1,%1};\n"::"r"(d),"r"(0):"memory");
}
__device__ __forceinline__ void ldsm4(u32& a0,u32& a1,u32& a2,u32& a3,u32 addr){
    asm volatile("ldmatrix.sync.aligned.m8n8.x4.shared.b16 {%0,%1,%2,%3},[%4];"
        :"=r"(a0),"=r"(a1),"=r"(a2),"=r"(a3):"r"(addr));
}
__device__ __forceinline__ void ldsm2t(u32& b0,u32& b1,u32 addr){
    asm volatile("ldmatrix.sync.aligned.m8n8.x2.trans.shared.b16 {%0,%1},[%2];"
        :"=r"(b0),"=r"(b1):"r"(addr));
}
__device__ __forceinline__ void mma16816(float* c,u32 a0,u32 a1,u32 a2,u32 a3,u32 b0,u32 b1){
    asm volatile("mma.sync.aligned.m16n8k16.row.col.f32.bf16.bf16.f32 "
        "{%0,%1,%2,%3},{%4,%5,%6,%7},{%8,%9},{%0,%1,%2,%3};"
        :"+f"(c[0]),"+f"(c[1]),"+f"(c[2]),"+f"(c[3])
        :"r"(a0),"r"(a1),"r"(a2),"r"(a3),"r"(b0),"r"(b1));
}

// smem layout (dynamic, 62720 B):
//   As: 2 planes x 40 rows x 272B   @ 0      (plane stride 10880)
//   Bs: 2 bufs x 2 planes x 128 x 80B @ 21760 (buf stride 20480, plane 10240)
//   Rs: 4KB fp32 reduction, aliases Bs buf1 @ 42240
#define SM_A1   10880
#define SM_B    21760
#define SM_BBUF 20480
#define SM_BPL  10240
#define SM_R    42240
#define SMEM_BYTES 62720

// ---------------------------------------------------------------------------
// One scan step: y[b,s_cur,p,oc] += relu(sum_{kw,ic} y[b,s_prev,p+kw-4,ic]*W[kw,ic,oc])
// Grid (4 postile, 4 octile, 8 b) = 128 blocks x 256 thr (8 warps).
// Warp = (khalf = wid>>2, ng = wid&3): ic half x 8-oc subtile; tile 32pos x 8oc.
// ---------------------------------------------------------------------------
template<int WS>
__global__ __launch_bounds__(256) void step_kernel(int s_cur, int s_prev, int dir)
{
    extern __shared__ __align__(1024) char smem[];
    const u32 sb = smem_u32(smem);
    const int tid = threadIdx.x, wid = tid>>5, lane = tid&31;
    const int khalf = wid>>2, ng = wid&3;
    const int p0 = blockIdx.x*32, oc0 = blockIdx.y*32, b = blockIdx.z;

    const __nv_bfloat16* Ah_src = (WS? g_p2h : g_p1h) + ((size_t)b*128 + s_prev)*16384;
    const __nv_bfloat16* Al_src = (WS? g_p2l : g_p1l) + ((size_t)b*128 + s_prev)*16384;
    const __nv_bfloat16* Wh = g_wh + (size_t)dir*9*16384;
    const __nv_bfloat16* Wl = g_wl + (size_t)dir*9*16384;

    // ---- Stage A window once: rows p0-4..p0+35, hi+lo planes ----
    #pragma unroll
    for (int q = 0; q < 5; ++q){
        int idx = tid + 256*q;                 // 1280 chunks of 16B
        int pi  = idx >= 640;
        int rem = idx - pi*640;
        int r = rem >> 4, j = rem & 15;
        int gp = p0 - 4 + r;
        u32 dst = sb + pi*SM_A1 + r*272 + j*16;
        if (gp >= 0 && gp < 128)
            cpa16(dst, (pi? Al_src : Ah_src) + (size_t)gp*128 + j*8);
        else
            sts16z(dst);
    }
    // ---- Stage B for kw into buf ----
    auto stageB = [&](int kw, int buf){
        #pragma unroll
        for (int q = 0; q < 4; ++q){
            int idx = tid + 256*q;             // 1024 chunks
            int pi = idx >> 9, rem = idx & 511;
            int ic = rem >> 2, j = rem & 3;
            u32 dst = sb + SM_B + buf*SM_BBUF + pi*SM_BPL + ic*80 + j*16;
            cpa16(dst, (pi? Wl : Wh) + (size_t)kw*16384 + (size_t)ic*128 + oc0 + j*8);
        }
    };
    stageB(0, 0);
    asm volatile("cp.async.commit_group;\n":::"memory");

    float c[2][4] = {{0,0,0,0},{0,0,0,0}};
    const int ar = lane & 15, ac = (lane>>4)*16;
    const int br = lane & 15;

    for (int kw = 0; kw < 9; ++kw){
        __syncthreads();                        // consumers of target buf done
        if (kw < 8) stageB(kw+1, (kw+1)&1);
        asm volatile("cp.async.commit_group;\n":::"memory");
        asm volatile("cp.async.wait_group 1;\n":::"memory");   // kw's data arrived
        __syncthreads();

        const int buf = kw & 1;
        const u32 A0 = sb, A1 = sb + SM_A1;
        const u32 B0 = sb + SM_B + buf*SM_BBUF, B1 = B0 + SM_BPL;

        #pragma unroll
        for (int ks = 0; ks < 4; ++ks){
            const int kb = khalf*64 + ks*16;
            u32 bh0,bh1,bl0,bl1;
            ldsm2t(bh0,bh1, B0 + (kb+br)*80 + ng*16);
            ldsm2t(bl0,bl1, B1 + (kb+br)*80 + ng*16);
            #pragma unroll
            for (int m = 0; m < 2; ++m){
                const u32 ra = (u32)(kw + 16*m + ar)*272 + kb*2 + ac;
                u32 h0,h1,h2,h3, l0,l1,l2,l3;
                ldsm4(h0,h1,h2,h3, A0 + ra);
                ldsm4(l0,l1,l2,l3, A1 + ra);
                mma16816(c[m], h0,h1,h2,h3, bh0,bh1);
                mma16816(c[m], h0,h1,h2,h3, bl0,bl1);
                mma16816(c[m], l0,l1,l2,l3, bh0,bh1);
            }
        }
    }
    __syncthreads();                            // all reads of As/Bs done

    // ---- Pairwise K-reduction (warp w+4 -> warp w) through smem ----
    float* Rs = (float*)(smem + SM_R);
    if (wid >= 4){
        const int s0 = (wid-4)*256;
        #pragma unroll
        for (int m = 0; m < 2; ++m)
            #pragma unroll
            for (int q = 0; q < 4; ++q)
                Rs[s0 + (m*4+q)*32 + lane] = c[m][q];
    }
    __syncthreads();
    if (wid < 4){
        const int s0 = wid*256;
        #pragma unroll
        for (int m = 0; m < 2; ++m)
            #pragma unroll
            for (int q = 0; q < 4; ++q)
                c[m][q] += Rs[s0 + (m*4+q)*32 + lane];

        // ---- Epilogue: relu-add into fp32 y, refresh hi/lo planes ----
        float* yw = WS? g_ws2 : g_ws1;
        __nv_bfloat16* oh = WS? g_p2h : g_p1h;
        __nv_bfloat16* ol = WS? g_p2l : g_p1l;
        const size_t rowbase = ((size_t)b*128 + s_cur)*128;
        const int oc = oc0 + ng*8 + 2*(lane & 3);
        #pragma unroll
        for (int m = 0; m < 2; ++m)
            #pragma unroll
            for (int hh = 0; hh < 2; ++hh){
                const int r = p0 + 16*m + (lane>>2) + hh*8;
                const size_t idx = (rowbase + r)*128 + oc;
                float2 cur = *(float2*)(yw + idx);
                float v0 = cur.x + fmaxf(c[m][2*hh+0], 0.f);
                float v1 = cur.y + fmaxf(c[m][2*hh+1], 0.f);
                *(float2*)(yw + idx) = make_float2(v0, v1);
                __nv_bfloat16 h0 = __float2bfloat16(v0);
                __nv_bfloat16 h1 = __float2bfloat16(v1);
                __nv_bfloat162 hp; hp.x = h0; hp.y = h1;
                *(__nv_bfloat162*)(oh + idx) = hp;
                __nv_bfloat162 lp;
                lp.x = __float2bfloat16(v0 - __bfloat162float(h0));
                lp.y = __float2bfloat16(v1 - __bfloat162float(h1));
                *(__nv_bfloat162*)(ol + idx) = lp;
            }
    }
}

// ---------------------------------------------------------------------------
// Weight split prep: fp32 [kw][ic][oc] -> bf16 hi/lo, same layout, 4 dirs.
// ---------------------------------------------------------------------------
__global__ void prep_w(const float* __restrict__ k0, const float* __restrict__ k1,
                       const float* __restrict__ k2, const float* __restrict__ k3)
{
    const size_t n = (size_t)36*16384;
    for (size_t i = (size_t)blockIdx.x*blockDim.x + threadIdx.x; i < n;
         i += (size_t)gridDim.x*blockDim.x){
        int z = (int)(i >> 14), rem = (int)(i & 16383);
        const float* s = (z < 9)? k0 : (z < 18)? k1 : (z < 27)? k2 : k3;
        float v = s[(size_t)(z % 9)*16384 + rem];
        __nv_bfloat16 h = __float2bfloat16(v);
        g_wh[i] = h;
        g_wl[i] = __float2bfloat16(v - __bfloat162float(h));
    }
}

// ---------------------------------------------------------------------------
// Transposes
// ---------------------------------------------------------------------------
__global__ void t_in(const float* __restrict__ x)
{
    __shared__ float t[32][33];
    const int bh = blockIdx.z, b = bh>>7, h = bh&127;
    const int w0 = blockIdx.x*32, c0 = blockIdx.y*32;
    const int tx = threadIdx.x, ty = threadIdx.y;
    const float* src = x + (((size_t)b*128 + c0)*128 + h)*128 + w0;
    #pragma unroll
    for (int i=0;i<4;++i){ int cc = ty*4+i; t[cc][tx] = src[(size_t)cc*16384 + tx]; }
    __syncthreads();
    const size_t base = (((size_t)b*128 + h)*128 + w0)*128 + c0;
    #pragma unroll
    for (int i=0;i<4;++i){
        int w = ty*4+i;
        float v = t[tx][w];
        size_t idx = base + (size_t)w*128 + tx;
        g_ws1[idx] = v;
        __nv_bfloat16 hv = __float2bfloat16(v);
        g_p1h[idx] = hv;
        g_p1l[idx] = __float2bfloat16(v - __bfloat162float(hv));
    }
}

__global__ void t_mid()
{
    const int b = blockIdx.z, h = blockIdx.y;
    const int w = blockIdx.x*blockDim.y + threadIdx.y;
    const int c4 = threadIdx.x;
    const size_t si = (((size_t)b*128 + h)*128 + w)*128 + c4*4;
    const size_t di = (((size_t)b*128 + w)*128 + h)*128 + c4*4;
    float4 v = *(const float4*)(g_ws1 + si);
    *(float4*)(g_ws2 + di) = v;
    float a[4] = {v.x, v.y, v.z, v.w};
    #pragma unroll
    for (int i=0;i<4;++i){
        __nv_bfloat16 hv = __float2bfloat16(a[i]);
        g_p2h[di+i] = hv;
        g_p2l[di+i] = __float2bfloat16(a[i] - __bfloat162float(hv));
    }
}

__global__ void t_out(float* __restrict__ out)
{
    __shared__ float t[32][33];
    const int bh = blockIdx.z, b = bh>>7, h = bh&127;
    const int w0 = blockIdx.x*32, c0 = blockIdx.y*32;
    const int tx = threadIdx.x, ty = threadIdx.y;
    const float* src = g_ws2 + (((size_t)b*128 + w0)*128 + h)*128 + c0;
    #pragma unroll
    for (int i=0;i<4;++i){ int w = ty*4+i; t[w][tx] = src[(size_t)w*16384 + tx]; }
    __syncthreads();
    float* d = out + (((size_t)b*128 + c0)*128 + h)*128 + w0;
    #pragma unroll
    for (int i=0;i<4;++i){ int cc = ty*4+i; d[(size_t)cc*16384 + tx] = t[tx][cc]; }
}

// ---------------------------------------------------------------------------
extern "C" void kernel_launch(void* const* d_in, const int* in_sizes, int n_in,
                              void* d_out, int out_size)
{
    const float* x    = (const float*)d_in[0];
    const float* k_td = (const float*)d_in[1];
    const float* k_dt = (const float*)d_in[2];
    const float* k_lr = (const float*)d_in[3];
    const float* k_rl = (const float*)d_in[4];
    float* out = (float*)d_out;

    static bool attr_done = false;
    if (!attr_done){
        cudaFuncSetAttribute(step_kernel<0>, cudaFuncAttributeMaxDynamicSharedMemorySize, SMEM_BYTES);
        cudaFuncSetAttribute(step_kernel<1>, cudaFuncAttributeMaxDynamicSharedMemorySize, SMEM_BYTES);
        attr_done = true;
    }

    const dim3 tb(32,8), tg(4,4,BB*HH);
    const dim3 sg(4,4,BB);   // 128 blocks

    prep_w<<<72,256>>>(k_td, k_dt, k_lr, k_rl);
    t_in<<<tg,tb>>>(x);

    for (int s=1; s<HH; ++s)
        step_kernel<0><<<sg,256,SMEM_BYTES>>>(s, s-1, 0);
    for (int s=HH-2; s>=0; --s)
        step_kernel<0><<<sg,256,SMEM_BYTES>>>(s, s+1, 1);

    t_mid<<<dim3(32,128,BB), dim3(32,4)>>>();

    for (int s=1; s<HH; ++s)
        step_kernel<1><<<sg,256,SMEM_BYTES>>>(s, s-1, 2);
    for (int s=HH-2; s>=0; --s)
        step_kernel<1><<<sg,256,SMEM_BYTES>>>(s, s+1, 3);

    t_out<<<tg,tb>>>(out);
}

// round 8
// speedup vs baseline: 1.3486x; 1.0169x over previous
#include <cuda_runtime.h>
#include <cuda_bf16.h>

#define BB 8
#define HH 128
typedef unsigned int u32;

// fp32 workspaces (ground truth) + bf16 hi/lo planes (MMA operands)
__device__ float g_ws1[(size_t)BB*128*128*128];
__device__ float g_ws2[(size_t)BB*128*128*128];
__device__ __align__(256) __nv_bfloat16 g_p1h[(size_t)BB*128*128*128];
__device__ __align__(256) __nv_bfloat16 g_p1l[(size_t)BB*128*128*128];
__device__ __align__(256) __nv_bfloat16 g_p2h[(size_t)BB*128*128*128];
__device__ __align__(256) __nv_bfloat16 g_p2l[(size_t)BB*128*128*128];
// Split weights, ORIGINAL layout [dir*9+kw][ic][oc]
__device__ __align__(256) __nv_bfloat16 g_wh[(size_t)36*128*128];
__device__ __align__(256) __nv_bfloat16 g_wl[(size_t)36*128*128];

// ---------------- helpers ----------------
__device__ __forceinline__ u32 smem_u32(const void* p){
    u32 a; asm("{ .reg .u64 t; cvta.to.shared.u64 t, %1; cvt.u32.u64 %0, t; }":"=r"(a):"l"(p)); return a;
}
__device__ __forceinline__ void cpa16(u32 d, const void* g){
    asm volatile("cp.async.ca.shared.global [%0],[%1],16;\n"::"r"(d),"l"(g));
}
__device__ __forceinline__ void sts16z(u32 d){
    asm volatile("st.shared.v4.b32 [%0],{%1,%1,%1,%1};\n"::"r"(d),"r"(0):"memory");
}
__device__ __forceinline__ void ldsm4(u32& a0,u32& a1,u32& a2,u32& a3,u32 addr){
    asm volatile("ldmatrix.sync.aligned.m8n8.x4.shared.b16 {%0,%1,%2,%3},[%4];"
        :"=r"(a0),"=r"(a1),"=r"(a2),"=r"(a3):"r"(addr));
}
__device__ __forceinline__ void ldsm2t(u32& b0,u32& b1,u32 addr){
    asm volatile("ldmatrix.sync.aligned.m8n8.x2.trans.shared.b16 {%0,%1},[%2];"
        :"=r"(b0),"=r"(b1):"r"(addr));
}
__device__ __forceinline__ void mma16816(float* c,u32 a0,u32 a1,u32 a2,u32 a3,u32 b0,u32 b1){
    asm volatile("mma.sync.aligned.m16n8k16.row.col.f32.bf16.bf16.f32 "
        "{%0,%1,%2,%3},{%4,%5,%6,%7},{%8,%9},{%0,%1,%2,%3};"
        :"+f"(c[0]),"+f"(c[1]),"+f"(c[2]),"+f"(c[3])
        :"r"(a0),"r"(a1),"r"(a2),"r"(a3),"r"(b0),"r"(b1));
}
__device__ __forceinline__ void waitg(int n){
    switch(n){
    case 0: asm volatile("cp.async.wait_group 0;\n":::"memory"); break;
    case 1: asm volatile("cp.async.wait_group 1;\n":::"memory"); break;
    case 2: asm volatile("cp.async.wait_group 2;\n":::"memory"); break;
    case 3: asm volatile("cp.async.wait_group 3;\n":::"memory"); break;
    case 4: asm volatile("cp.async.wait_group 4;\n":::"memory"); break;
    case 5: asm volatile("cp.async.wait_group 5;\n":::"memory"); break;
    case 6: asm volatile("cp.async.wait_group 6;\n":::"memory"); break;
    case 7: asm volatile("cp.async.wait_group 7;\n":::"memory"); break;
    default: asm volatile("cp.async.wait_group 8;\n":::"memory"); break;
    }
}

// smem layout (dynamic, 206080 B, opt-in):
//   A: 2 planes x 40 rows x 272B     @ 0       (plane stride 10880)
//   B: 9 kw x 2 planes x 128ic x 80B @ 21760   (kw stride 20480, plane 10240)
//   Rs: 8KB fp32 reduction scratch, aliases A  @ 0
#define SM_A1   10880
#define SM_B    21760
#define SM_BKW  20480
#define SM_BPL  10240
#define SMEM_BYTES 206080

// ---------------------------------------------------------------------------
// One scan step: y[b,s_cur,p,oc] += relu(sum_{kw,ic} y[b,s_prev,p+kw-4,ic]*W[kw,ic,oc])
// Grid (4 postile, 4 octile, 8 b) = 128 blocks x 512 thr (16 warps).
// Warp = (kq = wid>>2 : 32-ic quarter) x (ng = wid&3 : 8-oc subtile).
// Warp tile: 32 pos x 8 oc over its ic quarter; 2-stage pairwise reduction.
// All 9 kw of B staged upfront (9 cp.async groups), waited incrementally.
// ---------------------------------------------------------------------------
template<int WS>
__global__ __launch_bounds__(512) void step_kernel(int s_cur, int s_prev, int dir)
{
    extern __shared__ __align__(1024) char smem[];
    const u32 sb = smem_u32(smem);
    const int tid = threadIdx.x, wid = tid>>5, lane = tid&31;
    const int kq = wid>>2, ng = wid&3;
    const int p0 = blockIdx.x*32, oc0 = blockIdx.y*32, b = blockIdx.z;

    const __nv_bfloat16* Ah_src = (WS? g_p2h : g_p1h) + ((size_t)b*128 + s_prev)*16384;
    const __nv_bfloat16* Al_src = (WS? g_p2l : g_p1l) + ((size_t)b*128 + s_prev)*16384;
    const __nv_bfloat16* Wh = g_wh + (size_t)dir*9*16384;
    const __nv_bfloat16* Wl = g_wl + (size_t)dir*9*16384;

    // ---- Stage A window: rows p0-4..p0+35, hi+lo (1280 x 16B chunks) ----
    #pragma unroll
    for (int q = 0; q < 3; ++q){
        int idx = tid + 512*q;
        if (idx < 1280){
            int pi  = idx >= 640;
            int rem = idx - pi*640;
            int r = rem >> 4, j = rem & 15;
            int gp = p0 - 4 + r;
            u32 dst = sb + pi*SM_A1 + r*272 + j*16;
            if (gp >= 0 && gp < 128)
                cpa16(dst, (pi? Al_src : Ah_src) + (size_t)gp*128 + j*8);
            else
                sts16z(dst);
        }
    }
    // ---- Stage all 9 kw of B, one commit group per kw ----
    #pragma unroll
    for (int kw = 0; kw < 9; ++kw){
        #pragma unroll
        for (int q = 0; q < 2; ++q){
            int idx = tid + 512*q;               // 1024 chunks per kw
            int pi = idx >> 9, rem = idx & 511;
            int ic = rem >> 2, j = rem & 3;
            u32 dst = sb + SM_B + kw*SM_BKW + pi*SM_BPL + ic*80 + j*16;
            cpa16(dst, (pi? Wl : Wh) + (size_t)kw*16384 + (size_t)ic*128 + oc0 + j*8);
        }
        asm volatile("cp.async.commit_group;\n":::"memory");  // group kw (A rides group 0)
    }

    float c[2][4] = {{0,0,0,0},{0,0,0,0}};
    const int ar = lane & 15, ac = (lane>>4)*16;
    const int br = lane & 15;
    const u32 A0 = sb, A1 = sb + SM_A1;

    #pragma unroll
    for (int kw = 0; kw < 9; ++kw){
        waitg(8 - kw);        // groups 0..kw complete
        __syncthreads();      // make them visible across threads

        const u32 B0 = sb + SM_B + kw*SM_BKW, B1 = B0 + SM_BPL;
        #pragma unroll
        for (int ks = 0; ks < 2; ++ks){
            const int kb = kq*32 + ks*16;
            u32 bh0,bh1,bl0,bl1;
            ldsm2t(bh0,bh1, B0 + (u32)(kb+br)*80 + ng*16);
            ldsm2t(bl0,bl1, B1 + (u32)(kb+br)*80 + ng*16);
            #pragma unroll
            for (int m = 0; m < 2; ++m){
                const u32 ra = (u32)(kw + 16*m + ar)*272 + kb*2 + ac;
                u32 h0,h1,h2,h3, l0,l1,l2,l3;
                ldsm4(h0,h1,h2,h3, A0 + ra);
                ldsm4(l0,l1,l2,l3, A1 + ra);
                mma16816(c[m], h0,h1,h2,h3, bh0,bh1);
                mma16816(c[m], h0,h1,h2,h3, bl0,bl1);
                mma16816(c[m], l0,l1,l2,l3, bh0,bh1);
            }
        }
    }
    __syncthreads();          // all reads of A done before Rs alias-writes

    // ---- 2-stage pairwise K-reduction through smem (aliases A) ----
    float* Rs = (float*)smem;
    if (kq >= 2){
        const int s0 = ((kq-2)*4 + ng)*256;
        #pragma unroll
        for (int m = 0; m < 2; ++m)
            #pragma unroll
            for (int q = 0; q < 4; ++q)
                Rs[s0 + (m*4+q)*32 + lane] = c[m][q];
    }
    __syncthreads();
    if (kq < 2){
        const int s0 = (kq*4 + ng)*256;
        #pragma unroll
        for (int m = 0; m < 2; ++m)
            #pragma unroll
            for (int q = 0; q < 4; ++q)
                c[m][q] += Rs[s0 + (m*4+q)*32 + lane];
    }
    __syncthreads();
    if (kq == 1){
        const int s0 = ng*256;
        #pragma unroll
        for (int m = 0; m < 2; ++m)
            #pragma unroll
            for (int q = 0; q < 4; ++q)
                Rs[s0 + (m*4+q)*32 + lane] = c[m][q];
    }
    __syncthreads();
    if (kq == 0){
        const int s0 = ng*256;
        #pragma unroll
        for (int m = 0; m < 2; ++m)
            #pragma unroll
            for (int q = 0; q < 4; ++q)
                c[m][q] += Rs[s0 + (m*4+q)*32 + lane];

        // ---- Epilogue: relu-add into fp32 y, refresh hi/lo planes ----
        float* yw = WS? g_ws2 : g_ws1;
        __nv_bfloat16* oh = WS? g_p2h : g_p1h;
        __nv_bfloat16* ol = WS? g_p2l : g_p1l;
        const size_t rowbase = ((size_t)b*128 + s_cur)*128;
        const int oc = oc0 + ng*8 + 2*(lane & 3);
        #pragma unroll
        for (int m = 0; m < 2; ++m)
            #pragma unroll
            for (int hh = 0; hh < 2; ++hh){
                const int r = p0 + 16*m + (lane>>2) + hh*8;
                const size_t idx = (rowbase + r)*128 + oc;
                float2 cur = *(float2*)(yw + idx);
                float v0 = cur.x + fmaxf(c[m][2*hh+0], 0.f);
                float v1 = cur.y + fmaxf(c[m][2*hh+1], 0.f);
                *(float2*)(yw + idx) = make_float2(v0, v1);
                __nv_bfloat16 h0 = __float2bfloat16(v0);
                __nv_bfloat16 h1 = __float2bfloat16(v1);
                __nv_bfloat162 hp; hp.x = h0; hp.y = h1;
                *(__nv_bfloat162*)(oh + idx) = hp;
                __nv_bfloat162 lp;
                lp.x = __float2bfloat16(v0 - __bfloat162float(h0));
                lp.y = __float2bfloat16(v1 - __bfloat162float(h1));
                *(__nv_bfloat162*)(ol + idx) = lp;
            }
    }
}

// ---------------------------------------------------------------------------
// Weight split prep: fp32 [kw][ic][oc] -> bf16 hi/lo, same layout, 4 dirs.
// ---------------------------------------------------------------------------
__global__ void prep_w(const float* __restrict__ k0, const float* __restrict__ k1,
                       const float* __restrict__ k2, const float* __restrict__ k3)
{
    const size_t n = (size_t)36*16384;
    for (size_t i = (size_t)blockIdx.x*blockDim.x + threadIdx.x; i < n;
         i += (size_t)gridDim.x*blockDim.x){
        int z = (int)(i >> 14), rem = (int)(i & 16383);
        const float* s = (z < 9)? k0 : (z < 18)? k1 : (z < 27)? k2 : k3;
        float v = s[(size_t)(z % 9)*16384 + rem];
        __nv_bfloat16 h = __float2bfloat16(v);
        g_wh[i] = h;
        g_wl[i] = __float2bfloat16(v - __bfloat162float(h));
    }
}

// ---------------------------------------------------------------------------
// Transposes
// ---------------------------------------------------------------------------
__global__ void t_in(const float* __restrict__ x)
{
    __shared__ float t[32][33];
    const int bh = blockIdx.z, b = bh>>7, h = bh&127;
    const int w0 = blockIdx.x*32, c0 = blockIdx.y*32;
    const int tx = threadIdx.x, ty = threadIdx.y;
    const float* src = x + (((size_t)b*128 + c0)*128 + h)*128 + w0;
    #pragma unroll
    for (int i=0;i<4;++i){ int cc = ty*4+i; t[cc][tx] = src[(size_t)cc*16384 + tx]; }
    __syncthreads();
    const size_t base = (((size_t)b*128 + h)*128 + w0)*128 + c0;
    #pragma unroll
    for (int i=0;i<4;++i){
        int w = ty*4+i;
        float v = t[tx][w];
        size_t idx = base + (size_t)w*128 + tx;
        g_ws1[idx] = v;
        __nv_bfloat16 hv = __float2bfloat16(v);
        g_p1h[idx] = hv;
        g_p1l[idx] = __float2bfloat16(v - __bfloat162float(hv));
    }
}

__global__ void t_mid()
{
    const int b = blockIdx.z, h = blockIdx.y;
    const int w = blockIdx.x*blockDim.y + threadIdx.y;
    const int c4 = threadIdx.x;
    const size_t si = (((size_t)b*128 + h)*128 + w)*128 + c4*4;
    const size_t di = (((size_t)b*128 + w)*128 + h)*128 + c4*4;
    float4 v = *(const float4*)(g_ws1 + si);
    *(float4*)(g_ws2 + di) = v;
    float a[4] = {v.x, v.y, v.z, v.w};
    #pragma unroll
    for (int i=0;i<4;++i){
        __nv_bfloat16 hv = __float2bfloat16(a[i]);
        g_p2h[di+i] = hv;
        g_p2l[di+i] = __float2bfloat16(a[i] - __bfloat162float(hv));
    }
}

__global__ void t_out(float* __restrict__ out)
{
    __shared__ float t[32][33];
    const int bh = blockIdx.z, b = bh>>7, h = bh&127;
    const int w0 = blockIdx.x*32, c0 = blockIdx.y*32;
    const int tx = threadIdx.x, ty = threadIdx.y;
    const float* src = g_ws2 + (((size_t)b*128 + w0)*128 + h)*128 + c0;
    #pragma unroll
    for (int i=0;i<4;++i){ int w = ty*4+i; t[w][tx] = src[(size_t)w*16384 + tx]; }
    __syncthreads();
    float* d = out + (((size_t)b*128 + c0)*128 + h)*128 + w0;
    #pragma unroll
    for (int i=0;i<4;++i){ int cc = ty*4+i; d[(size_t)cc*16384 + tx] = t[tx][cc]; }
}

// ---------------------------------------------------------------------------
extern "C" void kernel_launch(void* const* d_in, const int* in_sizes, int n_in,
                              void* d_out, int out_size)
{
    const float* x    = (const float*)d_in[0];
    const float* k_td = (const float*)d_in[1];
    const float* k_dt = (const float*)d_in[2];
    const float* k_lr = (const float*)d_in[3];
    const float* k_rl = (const float*)d_in[4];
    float* out = (float*)d_out;

    static bool attr_done = false;
    if (!attr_done){
        cudaFuncSetAttribute(step_kernel<0>, cudaFuncAttributeMaxDynamicSharedMemorySize, SMEM_BYTES);
        cudaFuncSetAttribute(step_kernel<1>, cudaFuncAttributeMaxDynamicSharedMemorySize, SMEM_BYTES);
        attr_done = true;
    }

    const dim3 tb(32,8), tg(4,4,BB*HH);
    const dim3 sg(4,4,BB);   // 128 blocks

    prep_w<<<72,256>>>(k_td, k_dt, k_lr, k_rl);
    t_in<<<tg,tb>>>(x);

    for (int s=1; s<HH; ++s)
        step_kernel<0><<<sg,512,SMEM_BYTES>>>(s, s-1, 0);
    for (int s=HH-2; s>=0; --s)
        step_kernel<0><<<sg,512,SMEM_BYTES>>>(s, s+1, 1);

    t_mid<<<dim3(32,128,BB), dim3(32,4)>>>();

    for (int s=1; s<HH; ++s)
        step_kernel<1><<<sg,512,SMEM_BYTES>>>(s, s-1, 2);
    for (int s=HH-2; s>=0; --s)
        step_kernel<1><<<sg,512,SMEM_BYTES>>>(s, s+1, 3);

    t_out<<<tg,tb>>>(out);
}

// round 11
// speedup vs baseline: 1.7113x; 1.2690x over previous
#include <cuda_runtime.h>
#include <cuda_bf16.h>

#define BB 8
#define HH 128
typedef unsigned int u32;

// fp32 workspaces (ground truth) + bf16 hi/lo planes (MMA operands)
__device__ float g_ws1[(size_t)BB*128*128*128];
__device__ float g_ws2[(size_t)BB*128*128*128];
__device__ __align__(256) __nv_bfloat16 g_p1h[(size_t)BB*128*128*128];
__device__ __align__(256) __nv_bfloat16 g_p1l[(size_t)BB*128*128*128];
__device__ __align__(256) __nv_bfloat16 g_p2h[(size_t)BB*128*128*128];
__device__ __align__(256) __nv_bfloat16 g_p2l[(size_t)BB*128*128*128];
// Split weights, ORIGINAL layout [dir*9+kw][ic][oc]
__device__ __align__(256) __nv_bfloat16 g_wh[(size_t)36*128*128];
__device__ __align__(256) __nv_bfloat16 g_wl[(size_t)36*128*128];
// Row-completion counters: [scan(4)][b(8)][row(128)]
__device__ u32 g_cnt[4*8*128];

// ---------------- helpers ----------------
__device__ __forceinline__ u32 smem_u32(const void* p){
    u32 a; asm("{ .reg .u64 t; cvta.to.shared.u64 t, %1; cvt.u32.u64 %0, t; }":"=r"(a):"l"(p)); return a;
}
// L2-only async copy (bypasses non-coherent L1) — used for pipelined A data.
__device__ __forceinline__ void cpa16cg(u32 d, const void* g){
    asm volatile("cp.async.cg.shared.global [%0],[%1],16;\n"::"r"(d),"l"(g):"memory");
}
// L1-cached async copy — fine for read-only weights (written before launch).
__device__ __forceinline__ void cpa16(u32 d, const void* g){
    asm volatile("cp.async.ca.shared.global [%0],[%1],16;\n"::"r"(d),"l"(g):"memory");
}
__device__ __forceinline__ void sts16z(u32 d){
    asm volatile("st.shared.v4.b32 [%0],{%1,%1,%1,%1};\n"::"r"(d),"r"(0):"memory");
}
__device__ __forceinline__ void ldsm4(u32& a0,u32& a1,u32& a2,u32& a3,u32 addr){
    asm volatile("ldmatrix.sync.aligned.m8n8.x4.shared.b16 {%0,%1,%2,%3},[%4];"
        :"=r"(a0),"=r"(a1),"=r"(a2),"=r"(a3):"r"(addr));
}
__device__ __forceinline__ void ldsm2t(u32& b0,u32& b1,u32 addr){
    asm volatile("ldmatrix.sync.aligned.m8n8.x2.trans.shared.b16 {%0,%1},[%2];"
        :"=r"(b0),"=r"(b1):"r"(addr));
}
__device__ __forceinline__ void mma16816(float* c,u32 a0,u32 a1,u32 a2,u32 a3,u32 b0,u32 b1){
    asm volatile("mma.sync.aligned.m16n8k16.row.col.f32.bf16.bf16.f32 "
        "{%0,%1,%2,%3},{%4,%5,%6,%7},{%8,%9},{%0,%1,%2,%3};"
        :"+f"(c[0]),"+f"(c[1]),"+f"(c[2]),"+f"(c[3])
        :"r"(a0),"r"(a1),"r"(a2),"r"(a3),"r"(b0),"r"(b1));
}
// Proper atomics for the flag protocol (PTX memory model, gpu scope).
__device__ __forceinline__ u32 ld_acquire(const u32* p){
    u32 v;
    asm volatile("ld.acquire.gpu.global.b32 %0,[%1];" : "=r"(v) : "l"(p) : "memory");
    return v;
}
__device__ __forceinline__ void red_release_add(u32* p, u32 v){
    asm volatile("red.release.gpu.global.add.u32 [%0],%1;" :: "l"(p), "r"(v) : "memory");
}

// smem layout (dynamic, 206080 B, opt-in):
//   A : 2 planes x 40 rows x 272B      @ 0       (plane stride 10880)
//   W : 9 kw x 2 planes x 128ic x 80B  @ 21760   (kw stride 20480, plane 10240)
//   Rs: 8KB fp32 reduction scratch, aliases A    @ 0
#define SM_A1   10880
#define SM_W    21760
#define SM_WKW  20480
#define SM_WPL  10240
#define SMEM_BYTES 206080

// ---------------------------------------------------------------------------
// Persistent directional scan: 128 blocks (4 pt x 4 ot x 8 b) = one wave.
// Weights staged into smem ONCE; 127 steps pipelined via g_cnt row flags.
// Sync protocol (formally correct per PTX memory model):
//   producer: stores -> __threadfence() by ALL threads -> bar ->
//             tid0 red.release.gpu.add(cnt[row], 1)
//   consumer: tid0 spins ld.acquire.gpu until 16 -> bar ->
//             __threadfence() by ALL threads -> cp.async.cg (L2-only) loads
// ---------------------------------------------------------------------------
template<int WS>
__global__ __launch_bounds__(512) void scan_kernel(int dir, int rev, int scan_idx)
{
    extern __shared__ __align__(1024) char smem[];
    const u32 sb = smem_u32(smem);
    const int tid = threadIdx.x, wid = tid>>5, lane = tid&31;
    const int kq = wid>>2, ng = wid&3;
    const int p0 = blockIdx.x*32, oc0 = blockIdx.y*32, b = blockIdx.z;

    float* yw = WS? g_ws2 : g_ws1;
    __nv_bfloat16* ph = WS? g_p2h : g_p1h;
    __nv_bfloat16* pl = WS? g_p2l : g_p1l;
    const __nv_bfloat16* Wh = g_wh + (size_t)dir*9*16384;
    const __nv_bfloat16* Wl = g_wl + (size_t)dir*9*16384;
    u32* cnt = g_cnt + (scan_idx*8 + b)*128;

    // ---- Stage ALL weights once: 9 kw x 1024 chunks of 16B ----
    for (int t = tid; t < 9216; t += 512){
        int kw = t >> 10, idx = t & 1023;
        int pi = idx >> 9, rem = idx & 511;
        int ic = rem >> 2, j = rem & 3;
        u32 dst = sb + SM_W + kw*SM_WKW + pi*SM_WPL + ic*80 + j*16;
        cpa16(dst, (pi? Wl : Wh) + (size_t)kw*16384 + (size_t)ic*128 + oc0 + j*8);
    }
    asm volatile("cp.async.commit_group;\n":::"memory");
    asm volatile("cp.async.wait_group 0;\n":::"memory");
    __syncthreads();

    const int ar = lane & 15, ac = (lane>>4)*16;
    const int br = lane & 15;
    const u32 A0 = sb, A1 = sb + SM_A1;

    for (int i = 1; i < 128; ++i){
        const int row  = rev ? 127 - i : i;
        const int prev = rev ? row + 1 : row - 1;

        // ---- Wait for prev row completion (16 producer blocks of batch b) ----
        if (i > 1){
            if (tid == 0){
                while (ld_acquire(cnt + prev) < 16u) { }
            }
            __syncthreads();
            __threadfence();   // ALL threads: order subsequent data loads
        }

        // ---- Stage A window of prev row (L2-only cp.async.cg) ----
        const __nv_bfloat16* Ah_src = ph + ((size_t)b*128 + prev)*16384;
        const __nv_bfloat16* Al_src = pl + ((size_t)b*128 + prev)*16384;
        #pragma unroll
        for (int q = 0; q < 3; ++q){
            int idx = tid + 512*q;
            if (idx < 1280){
                int pi  = idx >= 640;
                int rem = idx - pi*640;
                int r = rem >> 4, j = rem & 15;
                int gp = p0 - 4 + r;
                u32 dst = sb + pi*SM_A1 + r*272 + j*16;
                if (gp >= 0 && gp < 128)
                    cpa16cg(dst, (pi? Al_src : Ah_src) + (size_t)gp*128 + j*8);
                else
                    sts16z(dst);
            }
        }
        asm volatile("cp.async.commit_group;\n":::"memory");
        asm volatile("cp.async.wait_group 0;\n":::"memory");
        __syncthreads();

        // ---- Compute: 9 kw, weights resident, no per-kw barriers ----
        float c[2][4] = {{0,0,0,0},{0,0,0,0}};
        #pragma unroll
        for (int kw = 0; kw < 9; ++kw){
            const u32 B0 = sb + SM_W + kw*SM_WKW, B1 = B0 + SM_WPL;
            #pragma unroll
            for (int ks = 0; ks < 2; ++ks){
                const int kb = kq*32 + ks*16;
                u32 bh0,bh1,bl0,bl1;
                ldsm2t(bh0,bh1, B0 + (u32)(kb+br)*80 + ng*16);
                ldsm2t(bl0,bl1, B1 + (u32)(kb+br)*80 + ng*16);
                #pragma unroll
                for (int m = 0; m < 2; ++m){
                    const u32 ra = (u32)(kw + 16*m + ar)*272 + kb*2 + ac;
                    u32 h0,h1,h2,h3, l0,l1,l2,l3;
                    ldsm4(h0,h1,h2,h3, A0 + ra);
                    ldsm4(l0,l1,l2,l3, A1 + ra);
                    mma16816(c[m], h0,h1,h2,h3, bh0,bh1);
                    mma16816(c[m], h0,h1,h2,h3, bl0,bl1);
                    mma16816(c[m], l0,l1,l2,l3, bh0,bh1);
                }
            }
        }
        __syncthreads();          // all A reads done before Rs alias-writes

        // ---- 2-stage pairwise K-reduction through smem (aliases A) ----
        float* Rs = (float*)smem;
        if (kq >= 2){
            const int s0 = ((kq-2)*4 + ng)*256;
            #pragma unroll
            for (int m = 0; m < 2; ++m)
                #pragma unroll
                for (int q = 0; q < 4; ++q)
                    Rs[s0 + (m*4+q)*32 + lane] = c[m][q];
        }
        __syncthreads();
        if (kq < 2){
            const int s0 = (kq*4 + ng)*256;
            #pragma unroll
            for (int m = 0; m < 2; ++m)
                #pragma unroll
                for (int q = 0; q < 4; ++q)
                    c[m][q] += Rs[s0 + (m*4+q)*32 + lane];
        }
        __syncthreads();
        if (kq == 1){
            const int s0 = ng*256;
            #pragma unroll
            for (int m = 0; m < 2; ++m)
                #pragma unroll
                for (int q = 0; q < 4; ++q)
                    Rs[s0 + (m*4+q)*32 + lane] = c[m][q];
        }
        __syncthreads();
        if (kq == 0){
            const int s0 = ng*256;
            #pragma unroll
            for (int m = 0; m < 2; ++m)
                #pragma unroll
                for (int q = 0; q < 4; ++q)
                    c[m][q] += Rs[s0 + (m*4+q)*32 + lane];

            // ---- Epilogue: relu-add into fp32 y, refresh hi/lo planes ----
            const size_t rowbase = ((size_t)b*128 + row)*128;
            const int oc = oc0 + ng*8 + 2*(lane & 3);
            #pragma unroll
            for (int m = 0; m < 2; ++m)
                #pragma unroll
                for (int hh = 0; hh < 2; ++hh){
                    const int r = p0 + 16*m + (lane>>2) + hh*8;
                    const size_t idx = (rowbase + r)*128 + oc;
                    float2 cur = *(float2*)(yw + idx);
                    float v0 = cur.x + fmaxf(c[m][2*hh+0], 0.f);
                    float v1 = cur.y + fmaxf(c[m][2*hh+1], 0.f);
                    *(float2*)(yw + idx) = make_float2(v0, v1);
                    __nv_bfloat16 h0 = __float2bfloat16(v0);
                    __nv_bfloat16 h1 = __float2bfloat16(v1);
                    __nv_bfloat162 hp; hp.x = h0; hp.y = h1;
                    *(__nv_bfloat162*)(ph + idx) = hp;
                    __nv_bfloat162 lp;
                    lp.x = __float2bfloat16(v0 - __bfloat162float(h0));
                    lp.y = __float2bfloat16(v1 - __bfloat162float(h1));
                    *(__nv_bfloat162*)(pl + idx) = lp;
                }
        }
        // ---- Publish: ALL threads fence, bar, then release-atomic flag ----
        __threadfence();
        __syncthreads();
        if (tid == 0)
            red_release_add(cnt + row, 1u);
    }
}

// ---------------------------------------------------------------------------
__global__ void zero_cnt()
{
    int i = blockIdx.x*blockDim.x + threadIdx.x;
    if (i < 4*8*128) g_cnt[i] = 0u;
}

// Weight split prep: fp32 [kw][ic][oc] -> bf16 hi/lo, same layout, 4 dirs.
__global__ void prep_w(const float* __restrict__ k0, const float* __restrict__ k1,
                       const float* __restrict__ k2, const float* __restrict__ k3)
{
    const size_t n = (size_t)36*16384;
    for (size_t i = (size_t)blockIdx.x*blockDim.x + threadIdx.x; i < n;
         i += (size_t)gridDim.x*blockDim.x){
        int z = (int)(i >> 14), rem = (int)(i & 16383);
        const float* s = (z < 9)? k0 : (z < 18)? k1 : (z < 27)? k2 : k3;
        float v = s[(size_t)(z % 9)*16384 + rem];
        __nv_bfloat16 h = __float2bfloat16(v);
        g_wh[i] = h;
        g_wl[i] = __float2bfloat16(v - __bfloat162float(h));
    }
}

// ---------------------------------------------------------------------------
// Transposes
// ---------------------------------------------------------------------------
__global__ void t_in(const float* __restrict__ x)
{
    __shared__ float t[32][33];
    const int bh = blockIdx.z, b = bh>>7, h = bh&127;
    const int w0 = blockIdx.x*32, c0 = blockIdx.y*32;
    const int tx = threadIdx.x, ty = threadIdx.y;
    const float* src = x + (((size_t)b*128 + c0)*128 + h)*128 + w0;
    #pragma unroll
    for (int i=0;i<4;++i){ int cc = ty*4+i; t[cc][tx] = src[(size_t)cc*16384 + tx]; }
    __syncthreads();
    const size_t base = (((size_t)b*128 + h)*128 + w0)*128 + c0;
    #pragma unroll
    for (int i=0;i<4;++i){
        int w = ty*4+i;
        float v = t[tx][w];
        size_t idx = base + (size_t)w*128 + tx;
        g_ws1[idx] = v;
        __nv_bfloat16 hv = __float2bfloat16(v);
        g_p1h[idx] = hv;
        g_p1l[idx] = __float2bfloat16(v - __bfloat162float(hv));
    }
}

__global__ void t_mid()
{
    const int b = blockIdx.z, h = blockIdx.y;
    const int w = blockIdx.x*blockDim.y + threadIdx.y;
    const int c4 = threadIdx.x;
    const size_t si = (((size_t)b*128 + h)*128 + w)*128 + c4*4;
    const size_t di = (((size_t)b*128 + w)*128 + h)*128 + c4*4;
    float4 v = *(const float4*)(g_ws1 + si);
    *(float4*)(g_ws2 + di) = v;
    float a[4] = {v.x, v.y, v.z, v.w};
    #pragma unroll
    for (int i=0;i<4;++i){
        __nv_bfloat16 hv = __float2bfloat16(a[i]);
        g_p2h[di+i] = hv;
        g_p2l[di+i] = __float2bfloat16(a[i] - __bfloat162float(hv));
    }
}

__global__ void t_out(float* __restrict__ out)
{
    __shared__ float t[32][33];
    const int bh = blockIdx.z, b = bh>>7, h = bh&127;
    const int w0 = blockIdx.x*32, c0 = blockIdx.y*32;
    const int tx = threadIdx.x, ty = threadIdx.y;
    const float* src = g_ws2 + (((size_t)b*128 + w0)*128 + h)*128 + c0;
    #pragma unroll
    for (int i=0;i<4;++i){ int w = ty*4+i; t[w][tx] = src[(size_t)w*16384 + tx]; }
    __syncthreads();
    float* d = out + (((size_t)b*128 + c0)*128 + h)*128 + w0;
    #pragma unroll
    for (int i=0;i<4;++i){ int cc = ty*4+i; d[(size_t)cc*16384 + tx] = t[tx][cc]; }
}

// ---------------------------------------------------------------------------
extern "C" void kernel_launch(void* const* d_in, const int* in_sizes, int n_in,
                              void* d_out, int out_size)
{
    const float* x    = (const float*)d_in[0];
    const float* k_td = (const float*)d_in[1];
    const float* k_dt = (const float*)d_in[2];
    const float* k_lr = (const float*)d_in[3];
    const float* k_rl = (const float*)d_in[4];
    float* out = (float*)d_out;

    static bool attr_done = false;
    if (!attr_done){
        cudaFuncSetAttribute(scan_kernel<0>, cudaFuncAttributeMaxDynamicSharedMemorySize, SMEM_BYTES);
        cudaFuncSetAttribute(scan_kernel<1>, cudaFuncAttributeMaxDynamicSharedMemorySize, SMEM_BYTES);
        attr_done = true;
    }

    const dim3 tb(32,8), tg(4,4,BB*HH);
    const dim3 sg(4,4,BB);   // 128 blocks: one co-resident wave

    zero_cnt<<<8,512>>>();
    prep_w<<<72,256>>>(k_td, k_dt, k_lr, k_rl);
    t_in<<<tg,tb>>>(x);

    scan_kernel<0><<<sg,512,SMEM_BYTES>>>(0, 0, 0);   // top-down
    scan_kernel<0><<<sg,512,SMEM_BYTES>>>(1, 1, 1);   // bottom-up

    t_mid<<<dim3(32,128,BB), dim3(32,4)>>>();

    scan_kernel<1><<<sg,512,SMEM_BYTES>>>(2, 0, 2);   // left-right
    scan_kernel<1><<<sg,512,SMEM_BYTES>>>(3, 1, 3);   // right-left

    t_out<<<tg,tb>>>(out);
}

// round 12
// speedup vs baseline: 2.0995x; 1.2269x over previous
#include <cuda_runtime.h>
#include <cuda_bf16.h>

#define BB 8
#define HH 128
typedef unsigned int u32;

// fp32 workspaces (ground truth) + bf16 hi/lo planes (MMA operands)
__device__ float g_ws1[(size_t)BB*128*128*128];
__device__ float g_ws2[(size_t)BB*128*128*128];
__device__ __align__(256) __nv_bfloat16 g_p1h[(size_t)BB*128*128*128];
__device__ __align__(256) __nv_bfloat16 g_p1l[(size_t)BB*128*128*128];
__device__ __align__(256) __nv_bfloat16 g_p2h[(size_t)BB*128*128*128];
__device__ __align__(256) __nv_bfloat16 g_p2l[(size_t)BB*128*128*128];
// Split weights, ORIGINAL layout [dir*9+kw][ic][oc]
__device__ __align__(256) __nv_bfloat16 g_wh[(size_t)36*128*128];
__device__ __align__(256) __nv_bfloat16 g_wl[(size_t)36*128*128];
// Row-completion counters: [scan(4)][b(8)][row(128)]
__device__ u32 g_cnt[4*8*128];

// ---------------- helpers ----------------
__device__ __forceinline__ u32 smem_u32(const void* p){
    u32 a; asm("{ .reg .u64 t; cvta.to.shared.u64 t, %1; cvt.u32.u64 %0, t; }":"=r"(a):"l"(p)); return a;
}
__device__ __forceinline__ void cpa16cg(u32 d, const void* g){
    asm volatile("cp.async.cg.shared.global [%0],[%1],16;\n"::"r"(d),"l"(g):"memory");
}
__device__ __forceinline__ void cpa16(u32 d, const void* g){
    asm volatile("cp.async.ca.shared.global [%0],[%1],16;\n"::"r"(d),"l"(g):"memory");
}
__device__ __forceinline__ void sts16z(u32 d){
    asm volatile("st.shared.v4.b32 [%0],{%1,%1,%1,%1};\n"::"r"(d),"r"(0):"memory");
}
__device__ __forceinline__ void ldsm4(u32& a0,u32& a1,u32& a2,u32& a3,u32 addr){
    asm volatile("ldmatrix.sync.aligned.m8n8.x4.shared.b16 {%0,%1,%2,%3},[%4];"
        :"=r"(a0),"=r"(a1),"=r"(a2),"=r"(a3):"r"(addr));
}
__device__ __forceinline__ void ldsm2t(u32& b0,u32& b1,u32 addr){
    asm volatile("ldmatrix.sync.aligned.m8n8.x2.trans.shared.b16 {%0,%1},[%2];"
        :"=r"(b0),"=r"(b1):"r"(addr));
}
__device__ __forceinline__ void mma16816(float* c,u32 a0,u32 a1,u32 a2,u32 a3,u32 b0,u32 b1){
    asm volatile("mma.sync.aligned.m16n8k16.row.col.f32.bf16.bf16.f32 "
        "{%0,%1,%2,%3},{%4,%5,%6,%7},{%8,%9},{%0,%1,%2,%3};"
        :"+f"(c[0]),"+f"(c[1]),"+f"(c[2]),"+f"(c[3])
        :"r"(a0),"r"(a1),"r"(a2),"r"(a3),"r"(b0),"r"(b1));
}
__device__ __forceinline__ u32 ld_acquire(const u32* p){
    u32 v;
    asm volatile("ld.acquire.gpu.global.b32 %0,[%1];" : "=r"(v) : "l"(p) : "memory");
    return v;
}
__device__ __forceinline__ void red_release_add(u32* p, u32 v){
    asm volatile("red.release.gpu.global.add.u32 [%0],%1;" :: "l"(p), "r"(v) : "memory");
}

// smem layout (dynamic, 206080 B, opt-in):
//   A : 2 planes x 40 rows x 272B      @ 0       (plane stride 10880)
//   W : 9 kw x 2 planes x 128ic x 80B  @ 21760   (kw stride 20480, plane 10240)
//   Rs partial: 8 subtiles x 128 f32   @ 0  (aliases A after compute)
//   Rs final  : 32 x 33 f32 tile       @ 4096
#define SM_A1   10880
#define SM_W    21760
#define SM_WKW  20480
#define SM_WPL  10240
#define SMEM_BYTES 206080

// ---------------------------------------------------------------------------
// Persistent directional scan: 128 blocks (4 pt x 4 ot x 8 b) = one wave.
// Weights staged once. 127 steps via g_cnt flags (release/acquire atomics).
// Warp = (kh = wid>>3 : 64-ic half) x (mh = (wid>>2)&1 : 16-pos half)
//        x (ng = wid&3 : 8-oc subtile). 1-stage pairwise K-reduction.
// ---------------------------------------------------------------------------
template<int WS>
__global__ __launch_bounds__(512) void scan_kernel(int dir, int rev, int scan_idx)
{
    extern __shared__ __align__(1024) char smem[];
    const u32 sb = smem_u32(smem);
    const int tid = threadIdx.x, wid = tid>>5, lane = tid&31;
    const int kh = wid>>3, mh = (wid>>2)&1, ng = wid&3;
    const int p0 = blockIdx.x*32, oc0 = blockIdx.y*32, b = blockIdx.z;

    float* yw = WS? g_ws2 : g_ws1;
    __nv_bfloat16* ph = WS? g_p2h : g_p1h;
    __nv_bfloat16* pl = WS? g_p2l : g_p1l;
    const __nv_bfloat16* Wh = g_wh + (size_t)dir*9*16384;
    const __nv_bfloat16* Wl = g_wl + (size_t)dir*9*16384;
    u32* cnt = g_cnt + (scan_idx*8 + b)*128;

    // ---- Stage ALL weights once ----
    for (int t = tid; t < 9216; t += 512){
        int kw = t >> 10, idx = t & 1023;
        int pi = idx >> 9, rem = idx & 511;
        int ic = rem >> 2, j = rem & 3;
        u32 dst = sb + SM_W + kw*SM_WKW + pi*SM_WPL + ic*80 + j*16;
        cpa16(dst, (pi? Wl : Wh) + (size_t)kw*16384 + (size_t)ic*128 + oc0 + j*8);
    }
    asm volatile("cp.async.commit_group;\n":::"memory");
    asm volatile("cp.async.wait_group 0;\n":::"memory");
    __syncthreads();

    const int ar = lane & 15, ac = (lane>>4)*16;
    const int br = lane & 15;
    const u32 A0 = sb, A1 = sb + SM_A1;
    // Epilogue mapping: thread t owns (pos = t>>4, oc pair = (t&15)*2)
    const int ep_pos = tid >> 4, ep_oc = (tid & 15)*2;

    for (int i = 1; i < 128; ++i){
        const int row  = rev ? 127 - i : i;
        const int prev = rev ? row + 1 : row - 1;
        const size_t rowbase = ((size_t)b*128 + row)*128;
        const size_t ep_idx  = (rowbase + p0 + ep_pos)*128 + oc0 + ep_oc;

        // Flag-independent prefetch: y[row] tile (RMW'd only by this block).
        float2 ypre = *(float2*)(yw + ep_idx);

        // ---- Wait for prev row completion (16 producer blocks of batch b) ----
        if (i > 1){
            if (tid == 0){
                while (ld_acquire(cnt + prev) < 16u) { }
                __threadfence();   // cheap single-thread safeguard
            }
            __syncthreads();
        }

        // ---- Stage A window of prev row (L2-only cp.async.cg) ----
        const __nv_bfloat16* Ah_src = ph + ((size_t)b*128 + prev)*16384;
        const __nv_bfloat16* Al_src = pl + ((size_t)b*128 + prev)*16384;
        #pragma unroll
        for (int q = 0; q < 3; ++q){
            int idx = tid + 512*q;
            if (idx < 1280){
                int pi  = idx >= 640;
                int rem = idx - pi*640;
                int r = rem >> 4, j = rem & 15;
                int gp = p0 - 4 + r;
                u32 dst = sb + pi*SM_A1 + r*272 + j*16;
                if (gp >= 0 && gp < 128)
                    cpa16cg(dst, (pi? Al_src : Ah_src) + (size_t)gp*128 + j*8);
                else
                    sts16z(dst);
            }
        }
        asm volatile("cp.async.commit_group;\n":::"memory");
        asm volatile("cp.async.wait_group 0;\n":::"memory");
        __syncthreads();

        // ---- Compute: 9 kw, warp covers 16pos x 8oc over its 64-ic half ----
        float c[4] = {0,0,0,0};
        #pragma unroll
        for (int kw = 0; kw < 9; ++kw){
            const u32 B0 = sb + SM_W + kw*SM_WKW, B1 = B0 + SM_WPL;
            #pragma unroll
            for (int ks = 0; ks < 4; ++ks){
                const int kb = kh*64 + ks*16;
                u32 bh0,bh1,bl0,bl1;
                ldsm2t(bh0,bh1, B0 + (u32)(kb+br)*80 + ng*16);
                ldsm2t(bl0,bl1, B1 + (u32)(kb+br)*80 + ng*16);
                const u32 ra = (u32)(kw + 16*mh + ar)*272 + kb*2 + ac;
                u32 h0,h1,h2,h3, l0,l1,l2,l3;
                ldsm4(h0,h1,h2,h3, A0 + ra);
                ldsm4(l0,l1,l2,l3, A1 + ra);
                mma16816(c, h0,h1,h2,h3, bh0,bh1);
                mma16816(c, h0,h1,h2,h3, bl0,bl1);
                mma16816(c, l0,l1,l2,l3, bh0,bh1);
            }
        }
        __syncthreads();          // all A reads done before Rs alias-writes

        // ---- 1-stage pairwise K-reduction (kh=1 -> kh=0) ----
        float* Rsp = (float*)smem;             // 8 x 128 partials
        float* Rsf = (float*)(smem + 4096);    // 32 x 33 final tile
        const int sub = wid & 7;
        if (kh == 1){
            #pragma unroll
            for (int q = 0; q < 4; ++q)
                Rsp[sub*128 + q*32 + lane] = c[q];
        }
        __syncthreads();
        if (kh == 0){
            #pragma unroll
            for (int q = 0; q < 4; ++q){
                c[q] += Rsp[sub*128 + q*32 + lane];
                int pos = mh*16 + (lane>>2) + 8*(q>>1);
                int oc  = ng*8 + 2*(lane&3) + (q&1);
                Rsf[pos*33 + oc] = c[q];
            }
        }
        __syncthreads();

        // ---- Coalesced epilogue by ALL 512 threads ----
        {
            float s0 = Rsf[ep_pos*33 + ep_oc];
            float s1 = Rsf[ep_pos*33 + ep_oc + 1];
            float v0 = ypre.x + fmaxf(s0, 0.f);
            float v1 = ypre.y + fmaxf(s1, 0.f);
            *(float2*)(yw + ep_idx) = make_float2(v0, v1);
            __nv_bfloat16 h0 = __float2bfloat16(v0);
            __nv_bfloat16 h1 = __float2bfloat16(v1);
            __nv_bfloat162 hp; hp.x = h0; hp.y = h1;
            *(__nv_bfloat162*)(ph + ep_idx) = hp;
            __nv_bfloat162 lp;
            lp.x = __float2bfloat16(v0 - __bfloat162float(h0));
            lp.y = __float2bfloat16(v1 - __bfloat162float(h1));
            *(__nv_bfloat162*)(pl + ep_idx) = lp;
        }

        // ---- Publish: bar (orders all threads' stores before release) ----
        __syncthreads();
        if (tid == 0)
            red_release_add(cnt + row, 1u);
    }
}

// ---------------------------------------------------------------------------
__global__ void zero_cnt()
{
    int i = blockIdx.x*blockDim.x + threadIdx.x;
    if (i < 4*8*128) g_cnt[i] = 0u;
}

// Weight split prep: fp32 [kw][ic][oc] -> bf16 hi/lo, same layout, 4 dirs.
__global__ void prep_w(const float* __restrict__ k0, const float* __restrict__ k1,
                       const float* __restrict__ k2, const float* __restrict__ k3)
{
    const size_t n = (size_t)36*16384;
    for (size_t i = (size_t)blockIdx.x*blockDim.x + threadIdx.x; i < n;
         i += (size_t)gridDim.x*blockDim.x){
        int z = (int)(i >> 14), rem = (int)(i & 16383);
        const float* s = (z < 9)? k0 : (z < 18)? k1 : (z < 27)? k2 : k3;
        float v = s[(size_t)(z % 9)*16384 + rem];
        __nv_bfloat16 h = __float2bfloat16(v);
        g_wh[i] = h;
        g_wl[i] = __float2bfloat16(v - __bfloat162float(h));
    }
}

// ---------------------------------------------------------------------------
// Transposes
// ---------------------------------------------------------------------------
__global__ void t_in(const float* __restrict__ x)
{
    __shared__ float t[32][33];
    const int bh = blockIdx.z, b = bh>>7, h = bh&127;
    const int w0 = blockIdx.x*32, c0 = blockIdx.y*32;
    const int tx = threadIdx.x, ty = threadIdx.y;
    const float* src = x + (((size_t)b*128 + c0)*128 + h)*128 + w0;
    #pragma unroll
    for (int i=0;i<4;++i){ int cc = ty*4+i; t[cc][tx] = src[(size_t)cc*16384 + tx]; }
    __syncthreads();
    const size_t base = (((size_t)b*128 + h)*128 + w0)*128 + c0;
    #pragma unroll
    for (int i=0;i<4;++i){
        int w = ty*4+i;
        float v = t[tx][w];
        size_t idx = base + (size_t)w*128 + tx;
        g_ws1[idx] = v;
        __nv_bfloat16 hv = __float2bfloat16(v);
        g_p1h[idx] = hv;
        g_p1l[idx] = __float2bfloat16(v - __bfloat162float(hv));
    }
}

__global__ void t_mid()
{
    const int b = blockIdx.z, h = blockIdx.y;
    const int w = blockIdx.x*blockDim.y + threadIdx.y;
    const int c4 = threadIdx.x;
    const size_t si = (((size_t)b*128 + h)*128 + w)*128 + c4*4;
    const size_t di = (((size_t)b*128 + w)*128 + h)*128 + c4*4;
    float4 v = *(const float4*)(g_ws1 + si);
    *(float4*)(g_ws2 + di) = v;
    float a[4] = {v.x, v.y, v.z, v.w};
    #pragma unroll
    for (int i=0;i<4;++i){
        __nv_bfloat16 hv = __float2bfloat16(a[i]);
        g_p2h[di+i] = hv;
        g_p2l[di+i] = __float2bfloat16(a[i] - __bfloat162float(hv));
    }
}

__global__ void t_out(float* __restrict__ out)
{
    __shared__ float t[32][33];
    const int bh = blockIdx.z, b = bh>>7, h = bh&127;
    const int w0 = blockIdx.x*32, c0 = blockIdx.y*32;
    const int tx = threadIdx.x, ty = threadIdx.y;
    const float* src = g_ws2 + (((size_t)b*128 + w0)*128 + h)*128 + c0;
    #pragma unroll
    for (int i=0;i<4;++i){ int w = ty*4+i; t[w][tx] = src[(size_t)w*16384 + tx]; }
    __syncthreads();
    float* d = out + (((size_t)b*128 + c0)*128 + h)*128 + w0;
    #pragma unroll
    for (int i=0;i<4;++i){ int cc = ty*4+i; d[(size_t)cc*16384 + tx] = t[tx][cc]; }
}

// ---------------------------------------------------------------------------
extern "C" void kernel_launch(void* const* d_in, const int* in_sizes, int n_in,
                              void* d_out, int out_size)
{
    const float* x    = (const float*)d_in[0];
    const float* k_td = (const float*)d_in[1];
    const float* k_dt = (const float*)d_in[2];
    const float* k_lr = (const float*)d_in[3];
    const float* k_rl = (const float*)d_in[4];
    float* out = (float*)d_out;

    static bool attr_done = false;
    if (!attr_done){
        cudaFuncSetAttribute(scan_kernel<0>, cudaFuncAttributeMaxDynamicSharedMemorySize, SMEM_BYTES);
        cudaFuncSetAttribute(scan_kernel<1>, cudaFuncAttributeMaxDynamicSharedMemorySize, SMEM_BYTES);
        attr_done = true;
    }

    const dim3 tb(32,8), tg(4,4,BB*HH);
    const dim3 sg(4,4,BB);   // 128 blocks: one co-resident wave

    zero_cnt<<<8,512>>>();
    prep_w<<<72,256>>>(k_td, k_dt, k_lr, k_rl);
    t_in<<<tg,tb>>>(x);

    scan_kernel<0><<<sg,512,SMEM_BYTES>>>(0, 0, 0);   // top-down
    scan_kernel<0><<<sg,512,SMEM_BYTES>>>(1, 1, 1);   // bottom-up

    t_mid<<<dim3(32,128,BB), dim3(32,4)>>>();

    scan_kernel<1><<<sg,512,SMEM_BYTES>>>(2, 0, 2);   // left-right
    scan_kernel<1><<<sg,512,SMEM_BYTES>>>(3, 1, 3);   // right-left

    t_out<<<tg,tb>>>(out);
}